// round 13
// baseline (speedup 1.0000x reference)
#include <cuda_runtime.h>
#include <math.h>
#include <stdint.h>

#define DM    1024
#define SEQ   1024
#define NHEAD 16
#define DK    64
#define MTOT  4096
#define BH    64

// ---------------- scratch (static device memory; no allocations) ----------
__device__ float g_xp[MTOT*DM];    // x + positional encoding (residual)
__device__ float g_q [MTOT*DM];
__device__ float g_k [MTOT*DM];
__device__ float g_vt[MTOT*DM];    // V transposed per head: [(b*1024+d)][s]
__device__ float g_o [MTOT*DM];    // attention output, heads merged
__device__ float g_attn_fallback[(size_t)BH*SEQ*SEQ];

// ---------------- tf32 helpers --------------------------------------------
__device__ __forceinline__ uint32_t f2tf(float f) {
    uint32_t u;
    asm("cvt.rna.tf32.f32 %0, %1;" : "=r"(u) : "f"(f));
    return u;
}

__device__ __forceinline__ void mma_tf32(float* c, const uint32_t* a, const uint32_t* b) {
    asm volatile(
        "mma.sync.aligned.m16n8k8.row.col.f32.tf32.tf32.f32 "
        "{%0,%1,%2,%3}, {%4,%5,%6,%7}, {%8,%9}, {%0,%1,%2,%3};"
        : "+f"(c[0]), "+f"(c[1]), "+f"(c[2]), "+f"(c[3])
        : "r"(a[0]), "r"(a[1]), "r"(a[2]), "r"(a[3]), "r"(b[0]), "r"(b[1]));
}

// ---------------- tf32 NT GEMM core, v2 -------------------------------------
// C[m,n] = sum_k A[m,k]*B[n,k]. 128 threads = 4 warps, warp tile WMxWN.
// BK=16, DOUBLE-buffered smem (one __syncthreads per iteration).
// smem rows stride LDSW=20 floats: fragment LDS bank = (20g + t) mod 32, all
// 32 distinct -> conflict-free; STS.128 ~2-way (acceptable).
template<int BM, int BN, int WMS, int WNS>
__device__ __forceinline__ void tc2(
    const float* __restrict__ A, int lda,
    const float* __restrict__ B, int ldb,
    int K, float* __restrict__ acc, float* __restrict__ smem)
{
    constexpr int BK = 16, LDSW = 20, NTH = 128;
    constexpr int WM = BM / WMS, WN = BN / WNS;
    constexpr int MT = WM / 16, NT = WN / 8;
    constexpr int ABUF = BM * LDSW, BBUF = BN * LDSW;
    constexpr int AF4 = (BM * BK) / (4 * NTH);
    constexpr int BF4 = (BN * BK) / (4 * NTH);

    float* As = smem;               // 2 buffers of ABUF
    float* Bs = smem + 2 * ABUF;    // 2 buffers of BBUF

    const int tid  = threadIdx.x;
    const int warp = tid >> 5, lane = tid & 31;
    const int g = lane >> 2, t = lane & 3;
    const int wm = (warp / WNS) * WM, wn = (warp % WNS) * WN;

    float4 ra[AF4], rb[BF4];

    auto ldg = [&](int k0) {
#pragma unroll
        for (int e = 0; e < AF4; e++) {
            int idx = e * NTH + tid;
            ra[e] = *(const float4*)(A + (size_t)(idx >> 2) * lda + k0 + (idx & 3) * 4);
        }
#pragma unroll
        for (int e = 0; e < BF4; e++) {
            int idx = e * NTH + tid;
            rb[e] = *(const float4*)(B + (size_t)(idx >> 2) * ldb + k0 + (idx & 3) * 4);
        }
    };
    auto sts = [&](int buf) {
#pragma unroll
        for (int e = 0; e < AF4; e++) {
            int idx = e * NTH + tid;
            uint4 u = make_uint4(f2tf(ra[e].x), f2tf(ra[e].y), f2tf(ra[e].z), f2tf(ra[e].w));
            *(uint4*)(As + buf * ABUF + (idx >> 2) * LDSW + (idx & 3) * 4) = u;
        }
#pragma unroll
        for (int e = 0; e < BF4; e++) {
            int idx = e * NTH + tid;
            uint4 u = make_uint4(f2tf(rb[e].x), f2tf(rb[e].y), f2tf(rb[e].z), f2tf(rb[e].w));
            *(uint4*)(Bs + buf * BBUF + (idx >> 2) * LDSW + (idx & 3) * 4) = u;
        }
    };

    ldg(0); sts(0);
    __syncthreads();

    const int nIter = K / BK;
    for (int it = 0; it < nIter; ++it) {
        bool more = (it + 1) < nIter;
        if (more) ldg((it + 1) * BK);              // LDG latency hidden by MMA below
        const float* a = As + (it & 1) * ABUF;
        const float* b = Bs + (it & 1) * BBUF;
#pragma unroll
        for (int kk = 0; kk < BK; kk += 8) {
            uint32_t af[MT][4], bf[NT][2];
#pragma unroll
            for (int i = 0; i < MT; i++) {
                const float* ap = a + (wm + i * 16 + g) * LDSW + kk + t;
                af[i][0] = __float_as_uint(ap[0]);
                af[i][1] = __float_as_uint(ap[8 * LDSW]);
                af[i][2] = __float_as_uint(ap[4]);
                af[i][3] = __float_as_uint(ap[8 * LDSW + 4]);
            }
#pragma unroll
            for (int j = 0; j < NT; j++) {
                const float* bp = b + (wn + j * 8 + g) * LDSW + kk + t;
                bf[j][0] = __float_as_uint(bp[0]);
                bf[j][1] = __float_as_uint(bp[4]);
            }
#pragma unroll
            for (int i = 0; i < MT; i++)
#pragma unroll
                for (int j = 0; j < NT; j++)
                    mma_tf32(&acc[(i * NT + j) * 4], af[i], bf[j]);
        }
        if (more) sts((it + 1) & 1);               // writes the buffer freed at it-1
        __syncthreads();
    }
}

// ---------------- positional encoding add ---------------------------------
__global__ void add_pe_kernel(const float* __restrict__ x) {
    int idx = blockIdx.x * blockDim.x + threadIdx.x;
    int d = idx & (DM - 1);
    int s = (idx >> 10) & (SEQ - 1);
    float ang = (float)s * expf(-(float)(d & ~1) * (9.210340371976184f / (float)DM));
    float pe = (d & 1) ? cosf(ang) : sinf(ang);
    g_xp[idx] = x[idx] + pe;
}

// ---------------- Q/K/V projections ----------------------------------------
// CTA 128x128, 4 warps of 64x64. MT=4, NT=8, acc=128 regs.
__global__ void __launch_bounds__(128)
qkv_kernel(const float* __restrict__ Wq,
           const float* __restrict__ Wk,
           const float* __restrict__ Wv)
{
    __shared__ __align__(16) float smem[4 * 128 * 20];   // 40960 B
    const int z = blockIdx.z;
    const float* W = (z == 0) ? Wq : ((z == 1) ? Wk : Wv);
    const int bm = blockIdx.y * 128, bn = blockIdx.x * 128;
    float acc[4 * 8 * 4] = {};
    tc2<128, 128, 2, 2>(g_xp + (size_t)bm * DM, DM, W + (size_t)bn * DM, DM, DM, acc, smem);

    const int warp = threadIdx.x >> 5, lane = threadIdx.x & 31;
    const int g = lane >> 2, t = lane & 3;
    const int wm = (warp >> 1) * 64, wn = (warp & 1) * 64;
    if (z < 2) {
        float* C = (z == 0) ? g_q : g_k;
#pragma unroll
        for (int i = 0; i < 4; i++)
#pragma unroll
            for (int j = 0; j < 8; j++) {
                float* a = &acc[(i * 8 + j) * 4];
                int m = bm + wm + i * 16 + g, n = bn + wn + j * 8 + t * 2;
                *(float2*)&C[(size_t)m * DM + n]       = make_float2(a[0], a[1]);
                *(float2*)&C[(size_t)(m + 8) * DM + n] = make_float2(a[2], a[3]);
            }
    } else {
        // V transposed per head: vt[(b*1024 + n)*1024 + s]
#pragma unroll
        for (int i = 0; i < 4; i++)
#pragma unroll
            for (int j = 0; j < 8; j++) {
                float* a = &acc[(i * 8 + j) * 4];
                int m = bm + wm + i * 16 + g, n = bn + wn + j * 8 + t * 2;
                int b = m >> 10, s = m & 1023;
                g_vt[((size_t)((b << 10) + n))     << 0] ; // (no-op guard removed below)
                g_vt[((size_t)((b << 10) + n))     * 1024 + s]     = a[0];
                g_vt[((size_t)((b << 10) + n + 1)) * 1024 + s]     = a[1];
                g_vt[((size_t)((b << 10) + n))     * 1024 + s + 8] = a[2];
                g_vt[((size_t)((b << 10) + n + 1)) * 1024 + s + 8] = a[3];
            }
    }
}

// ---------------- scores = (Q @ K^T)/8 per (b,h) ----------------------------
__global__ void __launch_bounds__(128)
scores_kernel(float* __restrict__ attn)
{
    __shared__ __align__(16) float smem[4 * 128 * 20];
    const int bh = blockIdx.z, b = bh >> 4, h = bh & 15;
    const int bm = blockIdx.y * 128, bn = blockIdx.x * 128;
    const float* A = g_q + (size_t)(b * SEQ + bm) * DM + h * DK;
    const float* B = g_k + (size_t)(b * SEQ + bn) * DM + h * DK;
    float* C = attn + (size_t)bh * SEQ * SEQ;
    float acc[4 * 8 * 4] = {};
    tc2<128, 128, 2, 2>(A, DM, B, DM, DK, acc, smem);

    const int warp = threadIdx.x >> 5, lane = threadIdx.x & 31;
    const int g = lane >> 2, t = lane & 3;
    const int wm = (warp >> 1) * 64, wn = (warp & 1) * 64;
#pragma unroll
    for (int i = 0; i < 4; i++)
#pragma unroll
        for (int j = 0; j < 8; j++) {
            float* a = &acc[(i * 8 + j) * 4];
            int m = bm + wm + i * 16 + g, n = bn + wn + j * 8 + t * 2;
            *(float2*)&C[(size_t)m * SEQ + n]       = make_float2(a[0] * 0.125f, a[1] * 0.125f);
            *(float2*)&C[(size_t)(m + 8) * SEQ + n] = make_float2(a[2] * 0.125f, a[3] * 0.125f);
        }
}

// ---------------- row softmax, in place (128 thr, 2 float4 each) ------------
__global__ void softmax_kernel(float* __restrict__ attn)
{
    __shared__ float red_max[4];
    __shared__ float red_sum[4];
    size_t row = blockIdx.x;
    float4* p = (float4*)(attn + row * SEQ);
    int tid = threadIdx.x;
    float4 v0 = p[tid];
    float4 v1 = p[tid + 128];
    float m = fmaxf(fmaxf(fmaxf(v0.x, v0.y), fmaxf(v0.z, v0.w)),
                    fmaxf(fmaxf(v1.x, v1.y), fmaxf(v1.z, v1.w)));
#pragma unroll
    for (int o = 16; o; o >>= 1) m = fmaxf(m, __shfl_xor_sync(0xFFFFFFFFu, m, o));
    if ((tid & 31) == 0) red_max[tid >> 5] = m;
    __syncthreads();
    float mm = fmaxf(fmaxf(red_max[0], red_max[1]), fmaxf(red_max[2], red_max[3]));
    v0.x = expf(v0.x - mm); v0.y = expf(v0.y - mm);
    v0.z = expf(v0.z - mm); v0.w = expf(v0.w - mm);
    v1.x = expf(v1.x - mm); v1.y = expf(v1.y - mm);
    v1.z = expf(v1.z - mm); v1.w = expf(v1.w - mm);
    float s = v0.x + v0.y + v0.z + v0.w + v1.x + v1.y + v1.z + v1.w;
#pragma unroll
    for (int o = 16; o; o >>= 1) s += __shfl_xor_sync(0xFFFFFFFFu, s, o);
    if ((tid & 31) == 0) red_sum[tid >> 5] = s;
    __syncthreads();
    float inv = 1.0f / (red_sum[0] + red_sum[1] + red_sum[2] + red_sum[3]);
    v0.x *= inv; v0.y *= inv; v0.z *= inv; v0.w *= inv;
    v1.x *= inv; v1.y *= inv; v1.z *= inv; v1.w *= inv;
    p[tid] = v0;
    p[tid + 128] = v1;
}

// ---------------- out = attn @ V per (b,h) ----------------------------------
// CTA 128x64, 4 warps of 64x32. MT=4, NT=4, acc=64 regs.
__global__ void __launch_bounds__(128)
pv_kernel(const float* __restrict__ attn)
{
    __shared__ __align__(16) float smem[2 * 128 * 20 + 2 * 64 * 20];  // 30720 B
    const int bh = blockIdx.z, b = bh >> 4, h = bh & 15;
    const int bm = blockIdx.y * 128;
    const float* A = attn + (size_t)bh * SEQ * SEQ + (size_t)bm * SEQ;
    const float* B = g_vt + (size_t)bh * DK * SEQ;      // rows = dk (64), k = s
    float acc[4 * 4 * 4] = {};
    tc2<128, 64, 2, 2>(A, SEQ, B, SEQ, SEQ, acc, smem);

    const int warp = threadIdx.x >> 5, lane = threadIdx.x & 31;
    const int g = lane >> 2, t = lane & 3;
    const int wm = (warp >> 1) * 64, wn = (warp & 1) * 32;
    float* C = g_o + (size_t)(b * SEQ) * DM + h * DK;
#pragma unroll
    for (int i = 0; i < 4; i++)
#pragma unroll
        for (int j = 0; j < 4; j++) {
            float* a = &acc[(i * 4 + j) * 4];
            int m = bm + wm + i * 16 + g, n = wn + j * 8 + t * 2;
            *(float2*)&C[(size_t)m * DM + n]       = make_float2(a[0], a[1]);
            *(float2*)&C[(size_t)(m + 8) * DM + n] = make_float2(a[2], a[3]);
        }
}

// ---------------- output projection + residual ------------------------------
__global__ void __launch_bounds__(128)
outproj_kernel(const float* __restrict__ Wo, float* __restrict__ y)
{
    __shared__ __align__(16) float smem[4 * 128 * 20];
    const int bm = blockIdx.y * 128, bn = blockIdx.x * 128;
    float acc[4 * 8 * 4] = {};
    tc2<128, 128, 2, 2>(g_o + (size_t)bm * DM, DM, Wo + (size_t)bn * DM, DM, DM, acc, smem);

    const int warp = threadIdx.x >> 5, lane = threadIdx.x & 31;
    const int g = lane >> 2, t = lane & 3;
    const int wm = (warp >> 1) * 64, wn = (warp & 1) * 64;
#pragma unroll
    for (int i = 0; i < 4; i++)
#pragma unroll
        for (int j = 0; j < 8; j++) {
            float* a = &acc[(i * 8 + j) * 4];
            int m = bm + wm + i * 16 + g, n = bn + wn + j * 8 + t * 2;
            size_t i0 = (size_t)m * DM + n, i1 = (size_t)(m + 8) * DM + n;
            float2 r0 = *(const float2*)&g_xp[i0];
            float2 r1 = *(const float2*)&g_xp[i1];
            *(float2*)&y[i0] = make_float2(a[0] + r0.x, a[1] + r0.y);
            *(float2*)&y[i1] = make_float2(a[2] + r1.x, a[3] + r1.y);
        }
}

// ---------------- LayerNorm, in place ----------------------------------------
__global__ void layernorm_kernel(float* __restrict__ y,
                                 const float* __restrict__ gamma,
                                 const float* __restrict__ beta)
{
    __shared__ float red_s[8];
    __shared__ float red_q[8];
    size_t row = blockIdx.x;
    float4* p = (float4*)(y + row * DM);
    int tid = threadIdx.x;
    float4 v = p[tid];
    float s = v.x + v.y + v.z + v.w;
    float q = v.x*v.x + v.y*v.y + v.z*v.z + v.w*v.w;
#pragma unroll
    for (int o = 16; o; o >>= 1) {
        s += __shfl_xor_sync(0xFFFFFFFFu, s, o);
        q += __shfl_xor_sync(0xFFFFFFFFu, q, o);
    }
    if ((tid & 31) == 0) { red_s[tid >> 5] = s; red_q[tid >> 5] = q; }
    __syncthreads();
    float S = 0.f, Q = 0.f;
#pragma unroll
    for (int i = 0; i < 8; i++) { S += red_s[i]; Q += red_q[i]; }
    float mean = S * (1.0f / DM);
    float var  = Q * (1.0f / DM) - mean * mean;
    float rstd = rsqrtf(var + 1e-6f);
    int base = tid * 4;
    float4 g = *(const float4*)(gamma + base);
    float4 bt = *(const float4*)(beta + base);
    v.x = (v.x - mean) * rstd * g.x + bt.x;
    v.y = (v.y - mean) * rstd * g.y + bt.y;
    v.z = (v.z - mean) * rstd * g.z + bt.z;
    v.w = (v.w - mean) * rstd * g.w + bt.w;
    p[tid] = v;
}

// ---------------- launch -----------------------------------------------------
extern "C" void kernel_launch(void* const* d_in, const int* in_sizes, int n_in,
                              void* d_out, int out_size)
{
    const float* x     = (const float*)d_in[0];
    const float* Wq    = (const float*)d_in[1];
    const float* Wk    = (const float*)d_in[2];
    const float* Wv    = (const float*)d_in[3];
    const float* Wo    = (const float*)d_in[4];
    const float* gamma = (const float*)d_in[5];
    const float* beta  = (const float*)d_in[6];

    float* y = (float*)d_out;
    const size_t y_elems    = (size_t)MTOT * DM;
    const size_t attn_elems = (size_t)BH * SEQ * SEQ;
    float* attn;
    if ((size_t)out_size >= y_elems + attn_elems) {
        attn = y + y_elems;
    } else {
        cudaGetSymbolAddress((void**)&attn, g_attn_fallback);
    }

    add_pe_kernel   <<< (MTOT * DM) / 256, 256 >>>(x);
    qkv_kernel      <<< dim3(DM/128, MTOT/128, 3), 128 >>>(Wq, Wk, Wv);
    scores_kernel   <<< dim3(SEQ/128, SEQ/128, BH), 128 >>>(attn);
    softmax_kernel  <<< BH * SEQ, 128 >>>(attn);
    pv_kernel       <<< dim3(1, SEQ/128, BH), 128 >>>(attn);
    outproj_kernel  <<< dim3(DM/128, MTOT/128), 128 >>>(Wo, y);
    layernorm_kernel<<< MTOT, 256 >>>(y, gamma, beta);
}

// round 14
// speedup vs baseline: 1.0019x; 1.0019x over previous
#include <cuda_runtime.h>
#include <math.h>
#include <stdint.h>

#define DM    1024
#define SEQ   1024
#define NHEAD 16
#define DK    64
#define MTOT  4096
#define BH    64

// ---------------- scratch (static device memory; no allocations) ----------
__device__ float g_xp[MTOT*DM];    // x + positional encoding (residual)
__device__ float g_q [MTOT*DM];
__device__ float g_k [MTOT*DM];
__device__ float g_vt[MTOT*DM];    // V transposed per head: [(b*1024+d)][s]
__device__ float g_o [MTOT*DM];    // attention output, heads merged
__device__ float g_attn_fallback[(size_t)BH*SEQ*SEQ];

// ---------------- tf32 helpers --------------------------------------------
__device__ __forceinline__ uint32_t f2tf(float f) {
    uint32_t u;
    asm("cvt.rna.tf32.f32 %0, %1;" : "=r"(u) : "f"(f));
    return u;
}

__device__ __forceinline__ void mma_tf32(float* c, const uint32_t* a, const uint32_t* b) {
    asm volatile(
        "mma.sync.aligned.m16n8k8.row.col.f32.tf32.tf32.f32 "
        "{%0,%1,%2,%3}, {%4,%5,%6,%7}, {%8,%9}, {%0,%1,%2,%3};"
        : "+f"(c[0]), "+f"(c[1]), "+f"(c[2]), "+f"(c[3])
        : "r"(a[0]), "r"(a[1]), "r"(a[2]), "r"(a[3]), "r"(b[0]), "r"(b[1]));
}

// ---------------- tf32 NT GEMM core, v2 -------------------------------------
// C[m,n] = sum_k A[m,k]*B[n,k]. 128 threads = 4 warps, warp tile WMxWN.
// BK=16, DOUBLE-buffered smem (one __syncthreads per iteration).
// smem rows stride LDSW=20 floats: fragment LDS bank = (20g + t) mod 32, all
// 32 distinct -> conflict-free; STS.128 ~2-way (acceptable).
template<int BM, int BN, int WMS, int WNS>
__device__ __forceinline__ void tc2(
    const float* __restrict__ A, int lda,
    const float* __restrict__ B, int ldb,
    int K, float* __restrict__ acc, float* __restrict__ smem)
{
    constexpr int BK = 16, LDSW = 20, NTH = 128;
    constexpr int WM = BM / WMS, WN = BN / WNS;
    constexpr int MT = WM / 16, NT = WN / 8;
    constexpr int ABUF = BM * LDSW, BBUF = BN * LDSW;
    constexpr int AF4 = (BM * BK) / (4 * NTH);
    constexpr int BF4 = (BN * BK) / (4 * NTH);

    float* As = smem;               // 2 buffers of ABUF
    float* Bs = smem + 2 * ABUF;    // 2 buffers of BBUF

    const int tid  = threadIdx.x;
    const int warp = tid >> 5, lane = tid & 31;
    const int g = lane >> 2, t = lane & 3;
    const int wm = (warp / WNS) * WM, wn = (warp % WNS) * WN;

    float4 ra[AF4], rb[BF4];

    auto ldg = [&](int k0) {
#pragma unroll
        for (int e = 0; e < AF4; e++) {
            int idx = e * NTH + tid;
            ra[e] = *(const float4*)(A + (size_t)(idx >> 2) * lda + k0 + (idx & 3) * 4);
        }
#pragma unroll
        for (int e = 0; e < BF4; e++) {
            int idx = e * NTH + tid;
            rb[e] = *(const float4*)(B + (size_t)(idx >> 2) * ldb + k0 + (idx & 3) * 4);
        }
    };
    auto sts = [&](int buf) {
#pragma unroll
        for (int e = 0; e < AF4; e++) {
            int idx = e * NTH + tid;
            uint4 u = make_uint4(f2tf(ra[e].x), f2tf(ra[e].y), f2tf(ra[e].z), f2tf(ra[e].w));
            *(uint4*)(As + buf * ABUF + (idx >> 2) * LDSW + (idx & 3) * 4) = u;
        }
#pragma unroll
        for (int e = 0; e < BF4; e++) {
            int idx = e * NTH + tid;
            uint4 u = make_uint4(f2tf(rb[e].x), f2tf(rb[e].y), f2tf(rb[e].z), f2tf(rb[e].w));
            *(uint4*)(Bs + buf * BBUF + (idx >> 2) * LDSW + (idx & 3) * 4) = u;
        }
    };

    ldg(0); sts(0);
    __syncthreads();

    const int nIter = K / BK;
    for (int it = 0; it < nIter; ++it) {
        bool more = (it + 1) < nIter;
        if (more) ldg((it + 1) * BK);              // LDG latency hidden by MMA below
        const float* a = As + (it & 1) * ABUF;
        const float* b = Bs + (it & 1) * BBUF;
#pragma unroll
        for (int kk = 0; kk < BK; kk += 8) {
            uint32_t af[MT][4], bf[NT][2];
#pragma unroll
            for (int i = 0; i < MT; i++) {
                const float* ap = a + (wm + i * 16 + g) * LDSW + kk + t;
                af[i][0] = __float_as_uint(ap[0]);
                af[i][1] = __float_as_uint(ap[8 * LDSW]);
                af[i][2] = __float_as_uint(ap[4]);
                af[i][3] = __float_as_uint(ap[8 * LDSW + 4]);
            }
#pragma unroll
            for (int j = 0; j < NT; j++) {
                const float* bp = b + (wn + j * 8 + g) * LDSW + kk + t;
                bf[j][0] = __float_as_uint(bp[0]);
                bf[j][1] = __float_as_uint(bp[4]);
            }
#pragma unroll
            for (int i = 0; i < MT; i++)
#pragma unroll
                for (int j = 0; j < NT; j++)
                    mma_tf32(&acc[(i * NT + j) * 4], af[i], bf[j]);
        }
        if (more) sts((it + 1) & 1);               // writes the buffer freed at it-1
        __syncthreads();
    }
}

// ---------------- positional encoding add ---------------------------------
__global__ void add_pe_kernel(const float* __restrict__ x) {
    int idx = blockIdx.x * blockDim.x + threadIdx.x;
    int d = idx & (DM - 1);
    int s = (idx >> 10) & (SEQ - 1);
    float ang = (float)s * expf(-(float)(d & ~1) * (9.210340371976184f / (float)DM));
    float pe = (d & 1) ? cosf(ang) : sinf(ang);
    g_xp[idx] = x[idx] + pe;
}

// ---------------- Q/K/V projections ----------------------------------------
// CTA 128x128, 4 warps of 64x64. MT=4, NT=8, acc=128 regs.
__global__ void __launch_bounds__(128)
qkv_kernel(const float* __restrict__ Wq,
           const float* __restrict__ Wk,
           const float* __restrict__ Wv)
{
    __shared__ __align__(16) float smem[4 * 128 * 20];   // 40960 B
    const int z = blockIdx.z;
    const float* W = (z == 0) ? Wq : ((z == 1) ? Wk : Wv);
    const int bm = blockIdx.y * 128, bn = blockIdx.x * 128;
    float acc[4 * 8 * 4] = {};
    tc2<128, 128, 2, 2>(g_xp + (size_t)bm * DM, DM, W + (size_t)bn * DM, DM, DM, acc, smem);

    const int warp = threadIdx.x >> 5, lane = threadIdx.x & 31;
    const int g = lane >> 2, t = lane & 3;
    const int wm = (warp >> 1) * 64, wn = (warp & 1) * 64;
    if (z < 2) {
        float* C = (z == 0) ? g_q : g_k;
#pragma unroll
        for (int i = 0; i < 4; i++)
#pragma unroll
            for (int j = 0; j < 8; j++) {
                float* a = &acc[(i * 8 + j) * 4];
                int m = bm + wm + i * 16 + g, n = bn + wn + j * 8 + t * 2;
                *(float2*)&C[(size_t)m * DM + n]       = make_float2(a[0], a[1]);
                *(float2*)&C[(size_t)(m + 8) * DM + n] = make_float2(a[2], a[3]);
            }
    } else {
        // V transposed per head: vt[(b*1024 + n)*1024 + s]
#pragma unroll
        for (int i = 0; i < 4; i++)
#pragma unroll
            for (int j = 0; j < 8; j++) {
                float* a = &acc[(i * 8 + j) * 4];
                int m = bm + wm + i * 16 + g, n = bn + wn + j * 8 + t * 2;
                int b = m >> 10, s = m & 1023;
                g_vt[((size_t)((b << 10) + n))     << 0] ; // (no-op guard removed below)
                g_vt[((size_t)((b << 10) + n))     * 1024 + s]     = a[0];
                g_vt[((size_t)((b << 10) + n + 1)) * 1024 + s]     = a[1];
                g_vt[((size_t)((b << 10) + n))     * 1024 + s + 8] = a[2];
                g_vt[((size_t)((b << 10) + n + 1)) * 1024 + s + 8] = a[3];
            }
    }
}

// ---------------- scores = (Q @ K^T)/8 per (b,h) ----------------------------
__global__ void __launch_bounds__(128)
scores_kernel(float* __restrict__ attn)
{
    __shared__ __align__(16) float smem[4 * 128 * 20];
    const int bh = blockIdx.z, b = bh >> 4, h = bh & 15;
    const int bm = blockIdx.y * 128, bn = blockIdx.x * 128;
    const float* A = g_q + (size_t)(b * SEQ + bm) * DM + h * DK;
    const float* B = g_k + (size_t)(b * SEQ + bn) * DM + h * DK;
    float* C = attn + (size_t)bh * SEQ * SEQ;
    float acc[4 * 8 * 4] = {};
    tc2<128, 128, 2, 2>(A, DM, B, DM, DK, acc, smem);

    const int warp = threadIdx.x >> 5, lane = threadIdx.x & 31;
    const int g = lane >> 2, t = lane & 3;
    const int wm = (warp >> 1) * 64, wn = (warp & 1) * 64;
#pragma unroll
    for (int i = 0; i < 4; i++)
#pragma unroll
        for (int j = 0; j < 8; j++) {
            float* a = &acc[(i * 8 + j) * 4];
            int m = bm + wm + i * 16 + g, n = bn + wn + j * 8 + t * 2;
            *(float2*)&C[(size_t)m * SEQ + n]       = make_float2(a[0] * 0.125f, a[1] * 0.125f);
            *(float2*)&C[(size_t)(m + 8) * SEQ + n] = make_float2(a[2] * 0.125f, a[3] * 0.125f);
        }
}

// ---------------- row softmax, in place (128 thr, 2 float4 each) ------------
__global__ void softmax_kernel(float* __restrict__ attn)
{
    __shared__ float red_max[4];
    __shared__ float red_sum[4];
    size_t row = blockIdx.x;
    float4* p = (float4*)(attn + row * SEQ);
    int tid = threadIdx.x;
    float4 v0 = p[tid];
    float4 v1 = p[tid + 128];
    float m = fmaxf(fmaxf(fmaxf(v0.x, v0.y), fmaxf(v0.z, v0.w)),
                    fmaxf(fmaxf(v1.x, v1.y), fmaxf(v1.z, v1.w)));
#pragma unroll
    for (int o = 16; o; o >>= 1) m = fmaxf(m, __shfl_xor_sync(0xFFFFFFFFu, m, o));
    if ((tid & 31) == 0) red_max[tid >> 5] = m;
    __syncthreads();
    float mm = fmaxf(fmaxf(red_max[0], red_max[1]), fmaxf(red_max[2], red_max[3]));
    v0.x = expf(v0.x - mm); v0.y = expf(v0.y - mm);
    v0.z = expf(v0.z - mm); v0.w = expf(v0.w - mm);
    v1.x = expf(v1.x - mm); v1.y = expf(v1.y - mm);
    v1.z = expf(v1.z - mm); v1.w = expf(v1.w - mm);
    float s = v0.x + v0.y + v0.z + v0.w + v1.x + v1.y + v1.z + v1.w;
#pragma unroll
    for (int o = 16; o; o >>= 1) s += __shfl_xor_sync(0xFFFFFFFFu, s, o);
    if ((tid & 31) == 0) red_sum[tid >> 5] = s;
    __syncthreads();
    float inv = 1.0f / (red_sum[0] + red_sum[1] + red_sum[2] + red_sum[3]);
    v0.x *= inv; v0.y *= inv; v0.z *= inv; v0.w *= inv;
    v1.x *= inv; v1.y *= inv; v1.z *= inv; v1.w *= inv;
    p[tid] = v0;
    p[tid + 128] = v1;
}

// ---------------- out = attn @ V per (b,h) ----------------------------------
// CTA 128x64, 4 warps of 64x32. MT=4, NT=4, acc=64 regs.
__global__ void __launch_bounds__(128)
pv_kernel(const float* __restrict__ attn)
{
    __shared__ __align__(16) float smem[2 * 128 * 20 + 2 * 64 * 20];  // 30720 B
    const int bh = blockIdx.z, b = bh >> 4, h = bh & 15;
    const int bm = blockIdx.y * 128;
    const float* A = attn + (size_t)bh * SEQ * SEQ + (size_t)bm * SEQ;
    const float* B = g_vt + (size_t)bh * DK * SEQ;      // rows = dk (64), k = s
    float acc[4 * 4 * 4] = {};
    tc2<128, 64, 2, 2>(A, SEQ, B, SEQ, SEQ, acc, smem);

    const int warp = threadIdx.x >> 5, lane = threadIdx.x & 31;
    const int g = lane >> 2, t = lane & 3;
    const int wm = (warp >> 1) * 64, wn = (warp & 1) * 32;
    float* C = g_o + (size_t)(b * SEQ) * DM + h * DK;
#pragma unroll
    for (int i = 0; i < 4; i++)
#pragma unroll
        for (int j = 0; j < 4; j++) {
            float* a = &acc[(i * 4 + j) * 4];
            int m = bm + wm + i * 16 + g, n = wn + j * 8 + t * 2;
            *(float2*)&C[(size_t)m * DM + n]       = make_float2(a[0], a[1]);
            *(float2*)&C[(size_t)(m + 8) * DM + n] = make_float2(a[2], a[3]);
        }
}

// ---------------- output projection + residual ------------------------------
__global__ void __launch_bounds__(128)
outproj_kernel(const float* __restrict__ Wo, float* __restrict__ y)
{
    __shared__ __align__(16) float smem[4 * 128 * 20];
    const int bm = blockIdx.y * 128, bn = blockIdx.x * 128;
    float acc[4 * 8 * 4] = {};
    tc2<128, 128, 2, 2>(g_o + (size_t)bm * DM, DM, Wo + (size_t)bn * DM, DM, DM, acc, smem);

    const int warp = threadIdx.x >> 5, lane = threadIdx.x & 31;
    const int g = lane >> 2, t = lane & 3;
    const int wm = (warp >> 1) * 64, wn = (warp & 1) * 64;
#pragma unroll
    for (int i = 0; i < 4; i++)
#pragma unroll
        for (int j = 0; j < 8; j++) {
            float* a = &acc[(i * 8 + j) * 4];
            int m = bm + wm + i * 16 + g, n = bn + wn + j * 8 + t * 2;
            size_t i0 = (size_t)m * DM + n, i1 = (size_t)(m + 8) * DM + n;
            float2 r0 = *(const float2*)&g_xp[i0];
            float2 r1 = *(const float2*)&g_xp[i1];
            *(float2*)&y[i0] = make_float2(a[0] + r0.x, a[1] + r0.y);
            *(float2*)&y[i1] = make_float2(a[2] + r1.x, a[3] + r1.y);
        }
}

// ---------------- LayerNorm, in place ----------------------------------------
__global__ void layernorm_kernel(float* __restrict__ y,
                                 const float* __restrict__ gamma,
                                 const float* __restrict__ beta)
{
    __shared__ float red_s[8];
    __shared__ float red_q[8];
    size_t row = blockIdx.x;
    float4* p = (float4*)(y + row * DM);
    int tid = threadIdx.x;
    float4 v = p[tid];
    float s = v.x + v.y + v.z + v.w;
    float q = v.x*v.x + v.y*v.y + v.z*v.z + v.w*v.w;
#pragma unroll
    for (int o = 16; o; o >>= 1) {
        s += __shfl_xor_sync(0xFFFFFFFFu, s, o);
        q += __shfl_xor_sync(0xFFFFFFFFu, q, o);
    }
    if ((tid & 31) == 0) { red_s[tid >> 5] = s; red_q[tid >> 5] = q; }
    __syncthreads();
    float S = 0.f, Q = 0.f;
#pragma unroll
    for (int i = 0; i < 8; i++) { S += red_s[i]; Q += red_q[i]; }
    float mean = S * (1.0f / DM);
    float var  = Q * (1.0f / DM) - mean * mean;
    float rstd = rsqrtf(var + 1e-6f);
    int base = tid * 4;
    float4 g = *(const float4*)(gamma + base);
    float4 bt = *(const float4*)(beta + base);
    v.x = (v.x - mean) * rstd * g.x + bt.x;
    v.y = (v.y - mean) * rstd * g.y + bt.y;
    v.z = (v.z - mean) * rstd * g.z + bt.z;
    v.w = (v.w - mean) * rstd * g.w + bt.w;
    p[tid] = v;
}

// ---------------- launch -----------------------------------------------------
extern "C" void kernel_launch(void* const* d_in, const int* in_sizes, int n_in,
                              void* d_out, int out_size)
{
    const float* x     = (const float*)d_in[0];
    const float* Wq    = (const float*)d_in[1];
    const float* Wk    = (const float*)d_in[2];
    const float* Wv    = (const float*)d_in[3];
    const float* Wo    = (const float*)d_in[4];
    const float* gamma = (const float*)d_in[5];
    const float* beta  = (const float*)d_in[6];

    float* y = (float*)d_out;
    const size_t y_elems    = (size_t)MTOT * DM;
    const size_t attn_elems = (size_t)BH * SEQ * SEQ;
    float* attn;
    if ((size_t)out_size >= y_elems + attn_elems) {
        attn = y + y_elems;
    } else {
        cudaGetSymbolAddress((void**)&attn, g_attn_fallback);
    }

    add_pe_kernel   <<< (MTOT * DM) / 256, 256 >>>(x);
    qkv_kernel      <<< dim3(DM/128, MTOT/128, 3), 128 >>>(Wq, Wk, Wv);
    scores_kernel   <<< dim3(SEQ/128, SEQ/128, BH), 128 >>>(attn);
    softmax_kernel  <<< BH * SEQ, 128 >>>(attn);
    pv_kernel       <<< dim3(1, SEQ/128, BH), 128 >>>(attn);
    outproj_kernel  <<< dim3(DM/128, MTOT/128), 128 >>>(Wo, y);
    layernorm_kernel<<< MTOT, 256 >>>(y, gamma, beta);
}